// round 17
// baseline (speedup 1.0000x reference)
#include <cuda_runtime.h>
#include <cuda_fp16.h>
#include <cstdint>

// B=4, S=4096, H=4096, E=64, topK=2 -> T=16384 tokens
#define HDIM 4096
#define EXP  64
#define HC   64                        // K per pipeline chunk
#define NCHUNKS (HDIM / HC)            // 64
#define TOK_PER_BLK 128
#define NTHREADS 384                   // warps 0-7 consumers, 8-11 producers

// A region: x1 fp16 SW128 (16KB) | x1q int8 (8KB) | x2q int8 (8KB)
#define X1H_OFF 0
#define X1Q_OFF 16384
#define X2Q_OFF 24576
#define A_REGION 32768
// B region: w1 fp16 SW128 (8KB) | w1q int8 (4KB) | w2q int8 (4KB)
#define W1H_OFF 0
#define W1Q_OFF 8192
#define W2Q_OFF 12288
#define B_REGION 16384
#define W_CHUNK_BYTES B_REGION
#define BUF_BYTES (A_REGION + B_REGION)        // 49152
#define SMEM_TOTAL (2 * BUF_BYTES)             // 98304

#define WSCALE 64.0f
#define INV_WSCALE 0.015625f
#define SQ1 16.0f            // int8 scale for primary (x1, w1)
#define SQ2 32768.0f         // int8 scale for residual (x2, w2)
#define INV_SC 1.90734863281e-6f   // 1 / (SQ1*SQ2) = 2^-19

__device__ float g_partials[256];
__device__ unsigned int g_done;
__device__ unsigned char g_w_sw[NCHUNKS * W_CHUNK_BYTES];  // 1 MB, L2-resident

// ---------------- helpers ----------------
__device__ __forceinline__ unsigned sw128(unsigned off) {
    return off ^ ((off >> 3) & 0x70);
}
// int8 tile swizzle: rows of 64B (k64), 2 rows packed per 128B line,
// 16B unit position XOR'd by line index (conflict-free for ldmatrix + stores).
__device__ __forceinline__ unsigned sw8(int row, int u) {
    return (unsigned)((row >> 1) * 128 +
                      (((((row & 1) << 2) | u) ^ ((row >> 1) & 7)) * 16));
}
__device__ __forceinline__ uint32_t h2u(__half2 h) {
    return *reinterpret_cast<uint32_t*>(&h);
}
__device__ __forceinline__ uint32_t pack_s8x4(float a, float b, float c, float d,
                                              float scale) {
    int ia, ib, ic, id;
    asm("cvt.rni.sat.s8.f32 %0, %1;" : "=r"(ia) : "f"(a * scale));
    asm("cvt.rni.sat.s8.f32 %0, %1;" : "=r"(ib) : "f"(b * scale));
    asm("cvt.rni.sat.s8.f32 %0, %1;" : "=r"(ic) : "f"(c * scale));
    asm("cvt.rni.sat.s8.f32 %0, %1;" : "=r"(id) : "f"(d * scale));
    uint32_t ab, cd, r;
    asm("prmt.b32 %0, %1, %2, 0x0040;" : "=r"(ab) : "r"(ia), "r"(ib));
    asm("prmt.b32 %0, %1, %2, 0x0040;" : "=r"(cd) : "r"(ic), "r"(id));
    asm("prmt.b32 %0, %1, %2, 0x5410;" : "=r"(r)  : "r"(ab), "r"(cd));
    return r;
}
__device__ __forceinline__ void cp16s(uint32_t dst, const void* src) {
    asm volatile("cp.async.cg.shared.global [%0], [%1], 16;" :: "r"(dst), "l"(src));
}
__device__ __forceinline__ void cp_commit() { asm volatile("cp.async.commit_group;"); }
__device__ __forceinline__ void cp_wait0()  { asm volatile("cp.async.wait_group 0;"); }

__device__ __forceinline__ void ldm4(uint32_t& r0, uint32_t& r1, uint32_t& r2,
                                     uint32_t& r3, uint32_t addr) {
    asm volatile("ldmatrix.sync.aligned.m8n8.x4.shared.b16 {%0,%1,%2,%3}, [%4];"
                 : "=r"(r0), "=r"(r1), "=r"(r2), "=r"(r3) : "r"(addr));
}
__device__ __forceinline__ void mma16816(float* d, const uint32_t* a, const uint32_t* b) {
    asm volatile(
        "mma.sync.aligned.m16n8k16.row.col.f32.f16.f16.f32 "
        "{%0,%1,%2,%3}, {%4,%5,%6,%7}, {%8,%9}, {%0,%1,%2,%3};"
        : "+f"(d[0]), "+f"(d[1]), "+f"(d[2]), "+f"(d[3])
        : "r"(a[0]), "r"(a[1]), "r"(a[2]), "r"(a[3]), "r"(b[0]), "r"(b[1]));
}
// int8 k32 correction MMA, exact s32 accumulation
__device__ __forceinline__ void mma16832i(int* d, const uint32_t* a, const uint32_t* b) {
    asm volatile(
        "mma.sync.aligned.m16n8k32.row.col.s32.s8.s8.s32 "
        "{%0,%1,%2,%3}, {%4,%5,%6,%7}, {%8,%9}, {%0,%1,%2,%3};"
        : "+r"(d[0]), "+r"(d[1]), "+r"(d[2]), "+r"(d[3])
        : "r"(a[0]), "r"(a[1]), "r"(a[2]), "r"(a[3]), "r"(b[0]), "r"(b[1]));
}

// ---------------- prologue: w -> fp16 split + int8 quants, per chunk ----------------
__global__ void prep_w(const float* __restrict__ gw) {
    int idx = blockIdx.x * blockDim.x + threadIdx.x;   // 64c*64e*16kw = 65536
    int kw = idx & 15;
    int e  = (idx >> 4) & 63;
    int c  = idx >> 10;
    float4 v = *reinterpret_cast<const float4*>(&gw[(size_t)e * HDIM + c * HC + kw * 4]);
    float Wx = v.x * WSCALE, Wy = v.y * WSCALE, Wz = v.z * WSCALE, Ww = v.w * WSCALE;
    unsigned char* base = g_w_sw + (size_t)c * W_CHUNK_BYTES;

    __half2 h1a = __floats2half2_rn(Wx, Wy);
    __half2 h1b = __floats2half2_rn(Wz, Ww);
    *reinterpret_cast<uint2*>(base + W1H_OFF + sw128((unsigned)(e * 128 + kw * 8))) =
        make_uint2(h2u(h1a), h2u(h1b));
    float2 f1a = __half22float2(h1a);
    float2 f1b = __half22float2(h1b);
    unsigned qoff = sw8(e, kw >> 2) + (kw & 3) * 4;
    *reinterpret_cast<uint32_t*>(base + W1Q_OFF + qoff) =
        pack_s8x4(f1a.x, f1a.y, f1b.x, f1b.y, SQ1);
    *reinterpret_cast<uint32_t*>(base + W2Q_OFF + qoff) =
        pack_s8x4(Wx - f1a.x, Wy - f1a.y, Wz - f1b.x, Ww - f1b.y, SQ2);
}

// ---------------- producer staging (128 threads: 16 rows each) ----------------
__device__ __forceinline__ void load_v(float4* v, const float* __restrict__ x,
                                       int tok0, int k0, int kq, int rowbase) {
    #pragma unroll
    for (int i = 0; i < 16; ++i)
        v[i] = *reinterpret_cast<const float4*>(
            &x[(size_t)(tok0 + rowbase + 8 * i) * HDIM + k0 + kq * 4]);
}
__device__ __forceinline__ void stage_x(unsigned char* buf, const float4* v,
                                        int kq, int rowbase) {
    const unsigned qbase = sw8(0, 0);  (void)qbase;
    #pragma unroll
    for (int i = 0; i < 16; ++i) {
        int r = rowbase + 8 * i;
        __half2 h1a = __floats2half2_rn(v[i].x, v[i].y);
        __half2 h1b = __floats2half2_rn(v[i].z, v[i].w);
        *reinterpret_cast<uint2*>(buf + X1H_OFF + sw128((unsigned)(r * 128 + kq * 8))) =
            make_uint2(h2u(h1a), h2u(h1b));
        float2 f1a = __half22float2(h1a);
        float2 f1b = __half22float2(h1b);
        unsigned qoff = sw8(r, kq >> 2) + (kq & 3) * 4;
        *reinterpret_cast<uint32_t*>(buf + X1Q_OFF + qoff) =
            pack_s8x4(f1a.x, f1a.y, f1b.x, f1b.y, SQ1);
        *reinterpret_cast<uint32_t*>(buf + X2Q_OFF + qoff) =
            pack_s8x4(v[i].x - f1a.x, v[i].y - f1a.y,
                      v[i].z - f1b.x, v[i].w - f1b.y, SQ2);
    }
}

// ---------------- main fused router ----------------
extern __shared__ unsigned char smem_raw[];

__global__ __launch_bounds__(NTHREADS, 1)
void router_kernel(const float* __restrict__ x, float* __restrict__ out, int T) {
    const int tid  = threadIdx.x;
    const int lane = tid & 31;
    const int warp = tid >> 5;          // 0..11
    const int tok0 = blockIdx.x * TOK_PER_BLK;
    const uint32_t sb = (uint32_t)__cvta_generic_to_shared(smem_raw);

    float acc[2][4][4];                 // main fp16 product, f32 acc
    int   accc[2][4][4];                // corrections, shared s32 acc
    float zsum = 0.f;

    if (warp >= 8) {
        // ================= PRODUCER warps 8-11 =================
        const int ptid    = tid - 256;
        const int kq      = ptid & 15;
        const int rowbase = ptid >> 4;
        float4 v[16];

        load_v(v, x, tok0, 0, kq, rowbase);
        #pragma unroll
        for (int i = 0; i < 8; ++i) {
            int lin = i * 128 + ptid;
            cp16s(sb + A_REGION + lin * 16, g_w_sw + lin * 16);
        }
        cp_commit();
        stage_x(smem_raw, v, kq, rowbase);
        load_v(v, x, tok0, HC, kq, rowbase);
        cp_wait0();
        __syncthreads();

        for (int c = 0; c < NCHUNKS; ++c) {
            if (c + 1 < NCHUNKS) {
                unsigned char* nbuf = smem_raw + ((c + 1) & 1) * BUF_BYTES;
                const uint32_t nbufu = sb + ((c + 1) & 1) * BUF_BYTES;
                const unsigned char* src = g_w_sw + (size_t)(c + 1) * W_CHUNK_BYTES;
                #pragma unroll
                for (int i = 0; i < 8; ++i) {
                    int lin = i * 128 + ptid;
                    cp16s(nbufu + A_REGION + lin * 16, src + lin * 16);
                }
                cp_commit();
                stage_x(nbuf, v, kq, rowbase);
                if (c + 2 < NCHUNKS)
                    load_v(v, x, tok0, (c + 2) * HC, kq, rowbase);
                cp_wait0();
            }
            __syncthreads();
        }
        __syncthreads();
        __syncthreads();
    } else {
        // ================= CONSUMER warps 0-7 (m32 x n32) =================
        const int mbase = (warp & 3) * 32;
        const int nbase = (warp >> 2) * 32;
        const int rl    = lane & 15;
        const int cb    = lane >> 4;
        const int arx   = rl & 7;
        const int browl = (lane & 7) + ((lane & 16) >> 1);
        const int bcb   = (lane >> 3) & 1;
        const int bxor  = lane & 7;
        // int8 ldmatrix lane coords
        const int i8row = lane & 15;        // A row within m16 tile
        const int i8hi  = lane >> 4;        // A k-unit offset
        const int i8brow = (lane & 7) + ((lane & 16) >> 1);  // B n-row within n16
        const int i8bhi  = (lane >> 3) & 1;                  // B k-unit offset

        #pragma unroll
        for (int mt = 0; mt < 2; ++mt)
            #pragma unroll
            for (int nt = 0; nt < 4; ++nt)
                #pragma unroll
                for (int r = 0; r < 4; ++r) { acc[mt][nt][r] = 0.f; accc[mt][nt][r] = 0; }

        __syncthreads();  // chunk 0 staged

        for (int c = 0; c < NCHUNKS; ++c) {
            const uint32_t Ab = sb + (c & 1) * BUF_BYTES;
            const uint32_t Bb = Ab + A_REGION;
            const uint32_t a_row_h = Ab + X1H_OFF + (mbase + rl) * 128;
            const uint32_t b_row_h = Bb + W1H_OFF + (nbase + browl) * 128;

            // ---- main product: fp16 x1*w1, 4 ksteps x 8 HMMA ----
            #pragma unroll
            for (int ks = 0; ks < 4; ++ks) {
                uint32_t bfh[8], afh[2][4];
                const uint32_t bcol = (uint32_t)(((2 * ks + bcb) ^ bxor) * 16);
                const uint32_t acol = (uint32_t)(((2 * ks + cb) ^ arx) * 16);
                ldm4(bfh[0], bfh[1], bfh[2], bfh[3], b_row_h + bcol);
                ldm4(bfh[4], bfh[5], bfh[6], bfh[7], b_row_h + 2048 + bcol);
                #pragma unroll
                for (int mt = 0; mt < 2; ++mt)
                    ldm4(afh[mt][0], afh[mt][1], afh[mt][2], afh[mt][3],
                         a_row_h + mt * 2048 + acol);
                #pragma unroll
                for (int mt = 0; mt < 2; ++mt)
                    #pragma unroll
                    for (int nt = 0; nt < 4; ++nt)
                        mma16816(acc[mt][nt], afh[mt], &bfh[nt * 2]);
            }

            // ---- corrections: int8 k32, 2 steps x 16 IMMA ----
            #pragma unroll
            for (int s = 0; s < 2; ++s) {
                uint32_t aq1[2][4], aq2[2][4], bq1[8], bq2[8];
                #pragma unroll
                for (int mt = 0; mt < 2; ++mt) {
                    unsigned ao = sw8(mbase + mt * 16 + i8row, 2 * s + i8hi);
                    ldm4(aq1[mt][0], aq1[mt][1], aq1[mt][2], aq1[mt][3],
                         Ab + X1Q_OFF + ao);
                    ldm4(aq2[mt][0], aq2[mt][1], aq2[mt][2], aq2[mt][3],
                         Ab + X2Q_OFF + ao);
                }
                #pragma unroll
                for (int nh = 0; nh < 2; ++nh) {
                    unsigned bo = sw8(nbase + nh * 16 + i8brow, 2 * s + i8bhi);
                    ldm4(bq1[nh * 4 + 0], bq1[nh * 4 + 1], bq1[nh * 4 + 2], bq1[nh * 4 + 3],
                         Bb + W1Q_OFF + bo);
                    ldm4(bq2[nh * 4 + 0], bq2[nh * 4 + 1], bq2[nh * 4 + 2], bq2[nh * 4 + 3],
                         Bb + W2Q_OFF + bo);
                }
                #pragma unroll
                for (int mt = 0; mt < 2; ++mt)
                    #pragma unroll
                    for (int nt = 0; nt < 4; ++nt) {
                        mma16832i(accc[mt][nt], aq1[mt], &bq2[nt * 2]);  // x1*w2
                        mma16832i(accc[mt][nt], aq2[mt], &bq1[nt * 2]);  // x2*w1
                    }
            }
            __syncthreads();
        }

        // ---- epilogue: (main + corr/2^19) descaled -> smem [128][68] ----
        float* ls = reinterpret_cast<float*>(smem_raw);
        #pragma unroll
        for (int mt = 0; mt < 2; ++mt) {
            int row0 = mbase + mt * 16 + (lane >> 2);
            #pragma unroll
            for (int nt = 0; nt < 4; ++nt) {
                int col = nbase + nt * 8 + (lane & 3) * 2;
                float l0 = (acc[mt][nt][0] + (float)accc[mt][nt][0] * INV_SC) * INV_WSCALE;
                float l1 = (acc[mt][nt][1] + (float)accc[mt][nt][1] * INV_SC) * INV_WSCALE;
                float l2 = (acc[mt][nt][2] + (float)accc[mt][nt][2] * INV_SC) * INV_WSCALE;
                float l3 = (acc[mt][nt][3] + (float)accc[mt][nt][3] * INV_SC) * INV_WSCALE;
                *reinterpret_cast<float2*>(&ls[row0 * 68 + col])       = make_float2(l0, l1);
                *reinterpret_cast<float2*>(&ls[(row0 + 8) * 68 + col]) = make_float2(l2, l3);
            }
        }
        __syncthreads();

        // one thread per token: top-2 + softmax + z partial
        if (tid < 128) {
            const float* row = &ls[tid * 68];
            float m = -3.402823466e38f; int i1 = 0;
            #pragma unroll 8
            for (int e = 0; e < EXP; ++e) {
                float vv = row[e];
                if (vv > m) { m = vv; i1 = e; }
            }
            float m2 = -3.402823466e38f; int i2 = 0;
            #pragma unroll 8
            for (int e = 0; e < EXP; ++e) {
                if (e == i1) continue;
                float vv = row[e];
                if (vv > m2) { m2 = vv; i2 = e; }
            }
            float Z = 0.f;
            #pragma unroll 8
            for (int e = 0; e < EXP; ++e) {
                float vv = row[e];
                Z += expf(vv - m);
                zsum += vv * vv;
            }
            int g = tok0 + tid;
            out[2 * g]     = (float)i1;
            out[2 * g + 1] = (float)i2;
            out[2 * T + 2 * g]     = 1.0f / Z;
            out[2 * T + 2 * g + 1] = expf(m2 - m) / Z;
        }
        reinterpret_cast<float*>(smem_raw + BUF_BYTES)[tid] = zsum;
        __syncthreads();
    }

    // ---- shared tail: deterministic z reduce ----
    float* zred = reinterpret_cast<float*>(smem_raw + BUF_BYTES);
    __shared__ unsigned int s_last;
    __syncthreads();
    #pragma unroll
    for (int s = 64; s > 0; s >>= 1) {
        if (tid < s) zred[tid] += zred[tid + s];
        __syncthreads();
    }
    if (tid == 0) {
        g_partials[blockIdx.x] = zred[0];
        __threadfence();
        unsigned prev = atomicAdd(&g_done, 1u);
        s_last = (prev == gridDim.x - 1) ? 1u : 0u;
    }
    __syncthreads();

    if (s_last) {
        __threadfence();
        if (tid < 128) zred[tid] = g_partials[tid];
        __syncthreads();
        #pragma unroll
        for (int s = 64; s > 0; s >>= 1) {
            if (tid < s) zred[tid] += zred[tid + s];
            __syncthreads();
        }
        if (tid == 0) {
            out[4 * T]     = 0.0f;                       // aux_loss
            out[4 * T + 1] = zred[0] / (float)(T * EXP); // z_loss
            g_done = 0;                                  // reset for graph replay
        }
    }
}

extern "C" void kernel_launch(void* const* d_in, const int* in_sizes, int n_in,
                              void* d_out, int out_size) {
    const float* x  = (const float*)d_in[0];
    const float* gw = (const float*)d_in[1];
    float* out = (float*)d_out;

    int T = in_sizes[0] / HDIM;            // 16384
    int blocks = T / TOK_PER_BLK;          // 128

    cudaFuncSetAttribute(router_kernel,
                         cudaFuncAttributeMaxDynamicSharedMemorySize, SMEM_TOTAL);

    prep_w<<<256, 256>>>(gw);
    router_kernel<<<blocks, NTHREADS, SMEM_TOTAL>>>(x, out, T);
}